// round 16
// baseline (speedup 1.0000x reference)
#include <cuda_runtime.h>
#include <cstdint>

// B=16, T=512, E=256, H=256, HEADS=8, NL=3, NC=10

// ---------------- scratch (static device memory) -----------------------------
__device__ __align__(16) float g_cat[8192*512];
__device__ __align__(16) float g_next[8192*256];
__device__ __align__(16) float g_xg[8192*768];
__device__ __align__(16) float g_out[8192*256];
__device__ __align__(16) float g_u[8192*256];
__device__ __align__(16) float g_a[8192*8];
__device__ __align__(16) float g_sent[16*256];

// ---------------- helpers ----------------------------------------------------
__device__ __forceinline__ uint32_t smem_u32(const void* p) {
    uint32_t a;
    asm("{ .reg .u64 t; cvta.to.shared.u64 t, %1; cvt.u32.u64 %0, t; }"
        : "=r"(a) : "l"(p));
    return a;
}
__device__ __forceinline__ uint32_t mapa_rank(uint32_t laddr, int rank) {
    uint32_t r;
    asm("mapa.shared::cluster.u32 %0, %1, %2;" : "=r"(r) : "r"(laddr), "r"(rank));
    return r;
}
__device__ __forceinline__ void st_async_f32(uint32_t raddr, float v, uint32_t rmbar) {
    asm volatile(
        "st.async.weak.shared::cluster.mbarrier::complete_tx::bytes.b32 [%0], %1, [%2];"
        :: "r"(raddr), "r"(__float_as_uint(v)), "r"(rmbar) : "memory");
}
// fast sigmoid / tanh built on MUFU (EX2 + RCP); rel err ~1e-6 — safe vs 1e-3
__device__ __forceinline__ float fast_sigmoid(float x) {
    return __fdividef(1.f, 1.f + __expf(-x));
}
__device__ __forceinline__ float fast_tanh(float x) {
    return __fdividef(2.f, 1.f + __expf(-2.f * x)) - 1.f;
}
// packed f32x2 FMA (Blackwell FFMA2): d = a*b + d, two lanes per instruction
__device__ __forceinline__ void fma2(unsigned long long& d,
                                     unsigned long long a, unsigned long long b) {
    asm("fma.rn.f32x2 %0, %1, %2, %0;" : "+l"(d) : "l"(a), "l"(b));
}
__device__ __forceinline__ unsigned long long pk2(float a, float b) {
    unsigned long long r;
    asm("mov.b64 %0, {%1, %2};" : "=l"(r) : "f"(a), "f"(b));
    return r;
}
__device__ __forceinline__ float sum2(unsigned long long v) {
    float lo, hi;
    asm("mov.b64 {%0, %1}, %2;" : "=f"(lo), "=f"(hi) : "l"(v));
    return lo + hi;
}

// ---------------- 1. embedding gather ----------------------------------------
__global__ void embed_kernel(const int* __restrict__ x, const float* __restrict__ emb) {
    int m = blockIdx.x;
    int tok = x[m];
    float4 v = *(const float4*)(emb + (size_t)tok * 256 + threadIdx.x * 4);
    *(float4*)(g_cat + (size_t)m * 512 + threadIdx.x * 4) = v;
}

// ---------------- fused mix + weighted GEMM (TN, per batch, fp32) ------------
__global__ void __launch_bounds__(256) wgemm_kernel(
    const float* __restrict__ G, const float* __restrict__ Gp,
    const float* __restrict__ mw)
{
    int b = blockIdx.z;
    const float* A0 = G  + (size_t)b * 3 * 262144;
    const float* P0 = Gp + (size_t)b * 3 * 262144;
    const float* Bp = g_cat + (size_t)b * 262144;
    float* C        = g_cat + (size_t)b * 262144 + 256;
    float w0 = mw[0], w1 = mw[1], w2 = mw[2];
    float u0 = 1.f - w0, u1 = 1.f - w1, u2 = 1.f - w2;

    __shared__ __align__(16) float As[16][132];
    __shared__ __align__(16) float Bs[16][68];
    int tid = threadIdx.x;
    int m0b = blockIdx.x * 128, n0b = blockIdx.y * 64;
    int tm = tid >> 4, tn = tid & 15;
    int akk = tid >> 4, amc = (tid & 15) * 8;
    int bkk = tid >> 4, bnc = (tid & 15) * 4;

    float acc[8][4];
#pragma unroll
    for (int i = 0; i < 8; ++i)
#pragma unroll
        for (int j = 0; j < 4; ++j) acc[i][j] = 0.f;

    for (int k0 = 0; k0 < 512; k0 += 16) {
        size_t off = (size_t)(k0 + akk) * 512 + m0b + amc;
        float4 m0, m1;
        {
            float4 ga0 = *(const float4*)(A0 + off);
            float4 ga1 = *(const float4*)(A0 + off + 4);
            float4 pa0 = *(const float4*)(P0 + off);
            float4 pa1 = *(const float4*)(P0 + off + 4);
            float4 gb0 = *(const float4*)(A0 + 262144 + off);
            float4 gb1 = *(const float4*)(A0 + 262144 + off + 4);
            float4 pb0 = *(const float4*)(P0 + 262144 + off);
            float4 pb1 = *(const float4*)(P0 + 262144 + off + 4);
            float4 gc0 = *(const float4*)(A0 + 524288 + off);
            float4 gc1 = *(const float4*)(A0 + 524288 + off + 4);
            float4 pc0 = *(const float4*)(P0 + 524288 + off);
            float4 pc1 = *(const float4*)(P0 + 524288 + off + 4);
            m0.x = w0*ga0.x + u0*pa0.x + w1*gb0.x + u1*pb0.x + w2*gc0.x + u2*pc0.x;
            m0.y = w0*ga0.y + u0*pa0.y + w1*gb0.y + u1*pb0.y + w2*gc0.y + u2*pc0.y;
            m0.z = w0*ga0.z + u0*pa0.z + w1*gb0.z + u1*pb0.z + w2*gc0.z + u2*pc0.z;
            m0.w = w0*ga0.w + u0*pa0.w + w1*gb0.w + u1*pb0.w + w2*gc0.w + u2*pc0.w;
            m1.x = w0*ga1.x + u0*pa1.x + w1*gb1.x + u1*pb1.x + w2*gc1.x + u2*pc1.x;
            m1.y = w0*ga1.y + u0*pa1.y + w1*gb1.y + u1*pb1.y + w2*gc1.y + u2*pc1.y;
            m1.z = w0*ga1.z + u0*pa1.z + w1*gb1.z + u1*pb1.z + w2*gc1.z + u2*pc1.z;
            m1.w = w0*ga1.w + u0*pa1.w + w1*gb1.w + u1*pb1.w + w2*gc1.w + u2*pc1.w;
        }
        float4 bv = *(const float4*)(Bp + (size_t)(k0 + bkk) * 512 + n0b + bnc);
        __syncthreads();
        *(float4*)&As[akk][amc]     = m0;
        *(float4*)&As[akk][amc + 4] = m1;
        *(float4*)&Bs[bkk][bnc]     = bv;
        __syncthreads();
#pragma unroll
        for (int kk = 0; kk < 16; ++kk) {
            float a8[8], b4[4];
            *(float4*)&a8[0] = *(const float4*)&As[kk][tm * 8];
            *(float4*)&a8[4] = *(const float4*)&As[kk][tm * 8 + 4];
            *(float4*)&b4[0] = *(const float4*)&Bs[kk][tn * 4];
#pragma unroll
            for (int i = 0; i < 8; ++i)
#pragma unroll
                for (int j = 0; j < 4; ++j)
                    acc[i][j] = fmaf(a8[i], b4[j], acc[i][j]);
        }
    }
#pragma unroll
    for (int i = 0; i < 8; ++i) {
        size_t row = (size_t)(m0b + tm * 8 + i) * 512 + n0b + tn * 4;
        float4 v = {acc[i][0], acc[i][1], acc[i][2], acc[i][3]};
        *(float4*)(C + row) = v;
    }
}

// ---------------- double-buffered NT GEMM (128x64 tile) ----------------------
// MODE: 0 plain, 1 +bias, 2 tanh(+bias)
template<int MODE>
__global__ void __launch_bounds__(256) gemm_nt(
    const float* __restrict__ A, int lda,
    const float* __restrict__ B, int ldb,
    float* __restrict__ C, int ldc, int K,
    const float* __restrict__ bias)
{
    __shared__ __align__(16) float As[2][16][132];
    __shared__ __align__(16) float Bs[2][16][68];
    int tid = threadIdx.x;
    int m0b = blockIdx.x * 128, n0b = blockIdx.y * 64;
    int tm = tid >> 4, tn = tid & 15;
    int ar = tid >> 1, akc = (tid & 1) * 8;
    int bn = tid >> 2, bkc = (tid & 3) * 4;
    const float* Ap  = A + (size_t)(m0b + ar) * lda + akc;
    const float* Bpp = B + (size_t)(n0b + bn) * ldb + bkc;

    float4 a0 = *(const float4*)(Ap);
    float4 a1 = *(const float4*)(Ap + 4);
    float4 b0 = *(const float4*)(Bpp);

    auto stage = [&](int buf) {
        As[buf][akc+0][ar] = a0.x; As[buf][akc+1][ar] = a0.y;
        As[buf][akc+2][ar] = a0.z; As[buf][akc+3][ar] = a0.w;
        As[buf][akc+4][ar] = a1.x; As[buf][akc+5][ar] = a1.y;
        As[buf][akc+6][ar] = a1.z; As[buf][akc+7][ar] = a1.w;
        Bs[buf][bkc+0][bn] = b0.x; Bs[buf][bkc+1][bn] = b0.y;
        Bs[buf][bkc+2][bn] = b0.z; Bs[buf][bkc+3][bn] = b0.w;
    };
    stage(0);
    __syncthreads();

    float acc[8][4];
#pragma unroll
    for (int i = 0; i < 8; ++i)
#pragma unroll
        for (int j = 0; j < 4; ++j) acc[i][j] = 0.f;

    int nt = K >> 4;
    for (int t = 0; t < nt; ++t) {
        int cur = t & 1;
        if (t + 1 < nt) {
            const float* Ap2  = Ap  + (t + 1) * 16;
            const float* Bpp2 = Bpp + (t + 1) * 16;
            a0 = *(const float4*)(Ap2);
            a1 = *(const float4*)(Ap2 + 4);
            b0 = *(const float4*)(Bpp2);
        }
#pragma unroll
        for (int kk = 0; kk < 16; ++kk) {
            float a8[8], b4[4];
            *(float4*)&a8[0] = *(const float4*)&As[cur][kk][tm * 8];
            *(float4*)&a8[4] = *(const float4*)&As[cur][kk][tm * 8 + 4];
            *(float4*)&b4[0] = *(const float4*)&Bs[cur][kk][tn * 4];
#pragma unroll
            for (int i = 0; i < 8; ++i)
#pragma unroll
                for (int j = 0; j < 4; ++j)
                    acc[i][j] = fmaf(a8[i], b4[j], acc[i][j]);
        }
        if (t + 1 < nt) {
            stage(cur ^ 1);
            __syncthreads();
        }
    }

    float bias4[4] = {0.f, 0.f, 0.f, 0.f};
    if (MODE >= 1) {
#pragma unroll
        for (int j = 0; j < 4; ++j) bias4[j] = bias[n0b + tn * 4 + j];
    }
#pragma unroll
    for (int i = 0; i < 8; ++i) {
        size_t row = (size_t)(m0b + tm * 8 + i) * ldc + n0b + tn * 4;
        float vv[4];
#pragma unroll
        for (int j = 0; j < 4; ++j) {
            float v = acc[i][j] + bias4[j];
            if (MODE == 2) v = tanhf(v);
            vv[j] = v;
        }
        float4 v4 = {vv[0], vv[1], vv[2], vv[3]};
        *(float4*)(C + row) = v4;
    }
}

// ---------------- fused GLU dual GEMM: next = (A@B1^T) * sigmoid(A@B2^T) -----
__global__ void __launch_bounds__(256) gemm_glu(
    const float* __restrict__ A, int lda,
    const float* __restrict__ B1, const float* __restrict__ B2, int ldb,
    float* __restrict__ C, int ldc, int K)
{
    __shared__ __align__(16) float As[2][16][132];
    __shared__ __align__(16) float Bs1[2][16][68];
    __shared__ __align__(16) float Bs2[2][16][68];
    int tid = threadIdx.x;
    int m0b = blockIdx.x * 128, n0b = blockIdx.y * 64;
    int tm = tid >> 4, tn = tid & 15;
    int ar = tid >> 1, akc = (tid & 1) * 8;
    int bn = tid >> 2, bkc = (tid & 3) * 4;
    const float* Ap  = A  + (size_t)(m0b + ar) * lda + akc;
    const float* Bp1 = B1 + (size_t)(n0b + bn) * ldb + bkc;
    const float* Bp2 = B2 + (size_t)(n0b + bn) * ldb + bkc;

    float4 a0 = *(const float4*)(Ap);
    float4 a1 = *(const float4*)(Ap + 4);
    float4 b0 = *(const float4*)(Bp1);
    float4 c0 = *(const float4*)(Bp2);

    auto stage = [&](int buf) {
        As[buf][akc+0][ar] = a0.x; As[buf][akc+1][ar] = a0.y;
        As[buf][akc+2][ar] = a0.z; As[buf][akc+3][ar] = a0.w;
        As[buf][akc+4][ar] = a1.x; As[buf][akc+5][ar] = a1.y;
        As[buf][akc+6][ar] = a1.z; As[buf][akc+7][ar] = a1.w;
        Bs1[buf][bkc+0][bn] = b0.x; Bs1[buf][bkc+1][bn] = b0.y;
        Bs1[buf][bkc+2][bn] = b0.z; Bs1[buf][bkc+3][bn] = b0.w;
        Bs2[buf][bkc+0][bn] = c0.x; Bs2[buf][bkc+1][bn] = c0.y;
        Bs2[buf][bkc+2][bn] = c0.z; Bs2[buf][bkc+3][bn] = c0.w;
    };
    stage(0);
    __syncthreads();

    float acc1[8][4], acc2[8][4];
#pragma unroll
    for (int i = 0; i < 8; ++i)
#pragma unroll
        for (int j = 0; j < 4; ++j) { acc1[i][j] = 0.f; acc2[i][j] = 0.f; }

    int nt = K >> 4;
    for (int t = 0; t < nt; ++t) {
        int cur = t & 1;
        if (t + 1 < nt) {
            a0 = *(const float4*)(Ap  + (t + 1) * 16);
            a1 = *(const float4*)(Ap  + (t + 1) * 16 + 4);
            b0 = *(const float4*)(Bp1 + (t + 1) * 16);
            c0 = *(const float4*)(Bp2 + (t + 1) * 16);
        }
#pragma unroll
        for (int kk = 0; kk < 16; ++kk) {
            float a8[8], b4[4], c4[4];
            *(float4*)&a8[0] = *(const float4*)&As[cur][kk][tm * 8];
            *(float4*)&a8[4] = *(const float4*)&As[cur][kk][tm * 8 + 4];
            *(float4*)&b4[0] = *(const float4*)&Bs1[cur][kk][tn * 4];
            *(float4*)&c4[0] = *(const float4*)&Bs2[cur][kk][tn * 4];
#pragma unroll
            for (int i = 0; i < 8; ++i)
#pragma unroll
                for (int j = 0; j < 4; ++j) {
                    acc1[i][j] = fmaf(a8[i], b4[j], acc1[i][j]);
                    acc2[i][j] = fmaf(a8[i], c4[j], acc2[i][j]);
                }
        }
        if (t + 1 < nt) {
            stage(cur ^ 1);
            __syncthreads();
        }
    }
#pragma unroll
    for (int i = 0; i < 8; ++i) {
        size_t row = (size_t)(m0b + tm * 8 + i) * ldc + n0b + tn * 4;
        float4 v;
        v.x = acc1[i][0] * fast_sigmoid(acc2[i][0]);
        v.y = acc1[i][1] * fast_sigmoid(acc2[i][1]);
        v.z = acc1[i][2] * fast_sigmoid(acc2[i][2]);
        v.w = acc1[i][3] * fast_sigmoid(acc2[i][3]);
        *(float4*)(C + row) = v;
    }
}

// ---------------- GRU scan: butterfly + distributed bcast + FFMA2 ------------
// R15 structure; the 96 scalar FFMAs are replaced by 48 packed fma.rn.f32x2
// (h tile reinterpreted as ulonglong2, W_hh pre-packed at init).
__global__ void __launch_bounds__(256, 1) __cluster_dims__(8, 1, 1)
scan_kernel(const float* __restrict__ xg, const float* __restrict__ Whh,
            const float* __restrict__ bhh, const float* __restrict__ h0)
{
    __shared__ __align__(16) float h[2][256];
    __shared__ __align__(8) unsigned long long mbar[2];
    int tid  = threadIdx.x;
    int rank = blockIdx.x & 7;
    int b    = blockIdx.x >> 3;
    int pair = tid >> 3;
    int sub  = tid & 7;
    int j    = rank * 32 + pair;

    // W_hh pre-packed as f32x2 pairs: w2[g][i] covers k = i*32 + sub*4 .. +3
    unsigned long long w2[3][8][2];
#pragma unroll
    for (int g = 0; g < 3; ++g) {
        const float* row = Whh + (size_t)(g * 256 + j) * 256;
#pragma unroll
        for (int i = 0; i < 8; ++i) {
            float4 v = *(const float4*)(row + i * 32 + sub * 4);
            w2[g][i][0] = pk2(v.x, v.y);
            w2[g][i][1] = pk2(v.z, v.w);
        }
    }
    float b_r = bhh[j], b_z = bhh[256 + j], b_n = bhh[512 + j];

    uint32_t barloc[2] = { smem_u32(&mbar[0]), smem_u32(&mbar[1]) };
    if (tid == 0) {
        asm volatile("mbarrier.init.shared.b64 [%0], 1;" :: "r"(barloc[0]) : "memory");
        asm volatile("mbarrier.init.shared.b64 [%0], 1;" :: "r"(barloc[1]) : "memory");
    }
    h[0][tid] = h0[b * 256 + tid];
    uint32_t hbase[2] = { smem_u32(&h[0][0]), smem_u32(&h[1][0]) };

    uint32_t raddr0 = mapa_rank(hbase[0] + (uint32_t)j * 4u, sub);
    uint32_t raddr1 = mapa_rank(hbase[1] + (uint32_t)j * 4u, sub);
    uint32_t rmbar0 = mapa_rank(barloc[0], sub);
    uint32_t rmbar1 = mapa_rank(barloc[1], sub);
    __syncthreads();
    asm volatile("barrier.cluster.arrive.aligned;" ::: "memory");
    asm volatile("barrier.cluster.wait.aligned;"  ::: "memory");

    const float* xrow0 = xg + (size_t)(b * 512) * 768;
    float xr = xrow0[j], xz = xrow0[256 + j], xn = xrow0[512 + j];

    for (int t = 0; t < 512; ++t) {
        int p = t & 1;
        if (tid == 0) {
            asm volatile("mbarrier.arrive.expect_tx.shared.b64 _, [%0], 1024;"
                         :: "r"(barloc[p]) : "memory");
        }
        float hold = h[p][j];
        unsigned long long ar2 = 0ull, az2 = 0ull, an2 = 0ull;
#pragma unroll
        for (int i = 0; i < 8; ++i) {
            ulonglong2 hv = *(const ulonglong2*)&h[p][i * 32 + sub * 4];
            fma2(ar2, w2[0][i][0], hv.x); fma2(ar2, w2[0][i][1], hv.y);
            fma2(az2, w2[1][i][0], hv.x); fma2(az2, w2[1][i][1], hv.y);
            fma2(an2, w2[2][i][0], hv.x); fma2(an2, w2[2][i][1], hv.y);
        }
        float ar = sum2(ar2), az = sum2(az2), an = sum2(an2);
        // butterfly: every lane ends with the full group sums
#pragma unroll
        for (int off = 4; off; off >>= 1) {
            ar += __shfl_xor_sync(0xffffffffu, ar, off, 8);
            az += __shfl_xor_sync(0xffffffffu, az, off, 8);
            an += __shfl_xor_sync(0xffffffffu, an, off, 8);
        }
        float r_ = fast_sigmoid(xr + ar + b_r);
        float z_ = fast_sigmoid(xz + az + b_z);
        float n_ = fast_tanh(xn + r_ * (an + b_n));
        float hv = (1.f - z_) * n_ + z_ * hold;
        // warp-parallel broadcast: one st.async per lane (to rank == sub)
        st_async_f32((p == 0) ? raddr1 : raddr0, hv, (p == 0) ? rmbar0 : rmbar1);
        if (sub == 0)
            g_out[(size_t)(b * 512 + t) * 256 + j] = hv;
        if (t < 511) {
            const float* xrow = xg + (size_t)(b * 512 + t + 1) * 768;
            xr = xrow[j]; xz = xrow[256 + j]; xn = xrow[512 + j];
        }
        {
            uint32_t parity = (uint32_t)((t >> 1) & 1);
            asm volatile(
                "{\n\t"
                ".reg .pred P1;\n\t"
                "WL_%=:\n\t"
                "mbarrier.try_wait.parity.acquire.cta.shared::cta.b64 P1, [%0], %1, 0x989680;\n\t"
                "@P1 bra.uni WD_%=;\n\t"
                "bra.uni WL_%=;\n\t"
                "WD_%=:\n\t"
                "}"
                :: "r"(barloc[p]), "r"(parity) : "memory");
        }
    }
}

// ---------------- attention logits: a = u @ W2^T + b2 ------------------------
__global__ void __launch_bounds__(256) logits_kernel(const float* __restrict__ W2,
                                                     const float* __restrict__ b2) {
    __shared__ float sW[8 * 256];
    for (int i = threadIdx.x; i < 2048; i += 256) sW[i] = W2[i];
    __syncthreads();
    int warp = threadIdx.x >> 5, lane = threadIdx.x & 31;
    int m = blockIdx.x * 8 + warp;
    const float* ur = g_u + (size_t)m * 256;
    float uv[8];
#pragma unroll
    for (int i = 0; i < 8; ++i) uv[i] = ur[i * 32 + lane];
#pragma unroll
    for (int hh = 0; hh < 8; ++hh) {
        float acc = 0.f;
#pragma unroll
        for (int i = 0; i < 8; ++i) acc = fmaf(uv[i], sW[hh * 256 + i * 32 + lane], acc);
#pragma unroll
        for (int off = 16; off; off >>= 1) acc += __shfl_down_sync(0xffffffffu, acc, off);
        if (lane == 0) g_a[(size_t)m * 8 + hh] = acc + b2[hh];
    }
}

// ---------------- masked softmax over T --------------------------------------
__global__ void softmax_kernel(const int* __restrict__ lengths, float* __restrict__ att) {
    int bh = blockIdx.x, b = bh >> 3, hh = bh & 7;
    int t = threadIdx.x;
    int len = lengths[b];
    float v = (t < len) ? g_a[(size_t)(b * 512 + t) * 8 + hh] : -1e30f;
    __shared__ float red[16];
    __shared__ float bc[2];
    float m = v;
#pragma unroll
    for (int o = 16; o; o >>= 1) m = fmaxf(m, __shfl_xor_sync(0xffffffffu, m, o));
    if ((t & 31) == 0) red[t >> 5] = m;
    __syncthreads();
    if (t == 0) {
        float mm = red[0];
        for (int i = 1; i < 16; ++i) mm = fmaxf(mm, red[i]);
        bc[0] = mm;
    }
    __syncthreads();
    float e = __expf(v - bc[0]);
    float s = e;
#pragma unroll
    for (int o = 16; o; o >>= 1) s += __shfl_xor_sync(0xffffffffu, s, o);
    __syncthreads();
    if ((t & 31) == 0) red[t >> 5] = s;
    __syncthreads();
    if (t == 0) {
        float ss = 0.f;
        for (int i = 0; i < 16; ++i) ss += red[i];
        bc[1] = ss;
    }
    __syncthreads();
    att[(size_t)bh * 512 + t] = e / bc[1];
}

// ---------------- sent + avg (+hn copy) --------------------------------------
__global__ void __launch_bounds__(256) sent_kernel(const float* __restrict__ att,
                                                   float* __restrict__ out_hn) {
    int b = blockIdx.x, q = blockIdx.y;
    __shared__ float sat[8][512];
    __shared__ float sred[4][8][64];
    int tid = threadIdx.x;
    for (int i = tid; i < 4096; i += 256) sat[i >> 9][i & 511] = att[(size_t)b * 4096 + i];
    __syncthreads();
    int dl = tid & 63, tc = tid >> 6;
    int d = q * 64 + dl;
    const float* orow = g_out + (size_t)b * 512 * 256;
    float acc[8] = {0.f,0.f,0.f,0.f,0.f,0.f,0.f,0.f};
    for (int t = tc * 128; t < tc * 128 + 128; ++t) {
        float ov = orow[(size_t)t * 256 + d];
#pragma unroll
        for (int hh = 0; hh < 8; ++hh) acc[hh] = fmaf(sat[hh][t], ov, acc[hh]);
    }
#pragma unroll
    for (int hh = 0; hh < 8; ++hh) sred[tc][hh][dl] = acc[hh];
    __syncthreads();
    if (tc == 0) {
        float s = 0.f;
#pragma unroll
        for (int hh = 0; hh < 8; ++hh)
            s += sred[0][hh][dl] + sred[1][hh][dl] + sred[2][hh][dl] + sred[3][hh][dl];
        g_sent[b * 256 + d] = s * 0.125f;
        out_hn[b * 256 + d] = orow[(size_t)511 * 256 + d];
    }
}

// ---------------- final FC ---------------------------------------------------
__global__ void fc_kernel(const float* __restrict__ Wf, const float* __restrict__ bf,
                          float* __restrict__ out_main) {
    int b = blockIdx.x;
    __shared__ float sv[256];
    sv[threadIdx.x] = g_sent[b * 256 + threadIdx.x];
    __syncthreads();
    if (threadIdx.x < 10) {
        float s = bf[threadIdx.x];
        for (int k = 0; k < 256; ++k) s = fmaf(Wf[threadIdx.x * 256 + k], sv[k], s);
        out_main[b * 10 + threadIdx.x] = s;
    }
}

// ============================================================================
extern "C" void kernel_launch(void* const* d_in, const int* in_sizes, int n_in,
                              void* d_out, int out_size) {
    const int*   x    = (const int*)  d_in[0];
    const int*   len  = (const int*)  d_in[1];
    const float* h0   = (const float*)d_in[2];
    const float* emb  = (const float*)d_in[3];
    const float* G    = (const float*)d_in[4];
    const float* Gp   = (const float*)d_in[5];
    const float* mw   = (const float*)d_in[6];
    const float* Wc1  = (const float*)d_in[7];
    const float* Wc2  = (const float*)d_in[8];
    const float* W_ih = (const float*)d_in[9];
    const float* W_hh = (const float*)d_in[10];
    const float* b_ih = (const float*)d_in[11];
    const float* b_hh = (const float*)d_in[12];
    const float* W1   = (const float*)d_in[13];
    const float* b1   = (const float*)d_in[14];
    const float* W2   = (const float*)d_in[15];
    const float* b2   = (const float*)d_in[16];
    const float* Wf   = (const float*)d_in[17];
    const float* bf   = (const float*)d_in[18];

    float* out      = (float*)d_out;
    float* out_main = out;
    float* out_hn   = out + 160;
    float* out_att  = out + 160 + 4096;

    void* p;
    cudaGetSymbolAddress(&p, g_cat);  float* pcat  = (float*)p;
    cudaGetSymbolAddress(&p, g_next); float* pnext = (float*)p;
    cudaGetSymbolAddress(&p, g_xg);   float* pxg   = (float*)p;
    cudaGetSymbolAddress(&p, g_out);  float* pout  = (float*)p;
    cudaGetSymbolAddress(&p, g_u);    float* pu    = (float*)p;

    // 1. embedding gather
    embed_kernel<<<8192, 64>>>(x, emb);
    // 2+3. fused mix + weighted GEMM
    wgemm_kernel<<<dim3(4, 4, 16), 256>>>(G, Gp, mw);
    // 4+5. fused GLU: next = (cat@Wc1^T) * sigmoid(cat@Wc2^T)
    gemm_glu<<<dim3(64, 4), 256>>>(pcat, 512, Wc1, Wc2, 512, pnext, 256, 512);
    // 6. xg = next @ W_ih^T + b_ih
    gemm_nt<1><<<dim3(64, 12), 256>>>(pnext, 256, W_ih, 256, pxg, 768, 256, b_ih);
    // 7. GRU scan (butterfly + distributed bcast + FFMA2)
    scan_kernel<<<128, 256>>>(pxg, W_hh, b_hh, h0);
    // 8. u = tanh(out @ W1^T + b1)
    gemm_nt<2><<<dim3(64, 4), 256>>>(pout, 256, W1, 256, pu, 256, 256, b1);
    // 9. logits
    logits_kernel<<<1024, 256>>>(W2, b2);
    // 10. masked softmax
    softmax_kernel<<<128, 512>>>(len, out_att);
    // 11. sent + avg + hn
    sent_kernel<<<dim3(16, 4), 256>>>(out_att, out_hn);
    // 12. final FC
    fc_kernel<<<16, 256>>>(Wf, bf, out_main);
}

// round 17
// speedup vs baseline: 1.0299x; 1.0299x over previous
#include <cuda_runtime.h>
#include <cstdint>

// B=16, T=512, E=256, H=256, HEADS=8, NL=3, NC=10

// ---------------- scratch (static device memory) -----------------------------
__device__ __align__(16) float g_cat[8192*512];
__device__ __align__(16) float g_next[8192*256];
__device__ __align__(16) float g_xg[8192*768];
__device__ __align__(16) float g_out[8192*256];
__device__ __align__(16) float g_u[8192*256];
__device__ __align__(16) float g_a[8192*8];
__device__ __align__(16) float g_sent[16*256];

// ---------------- helpers ----------------------------------------------------
__device__ __forceinline__ uint32_t smem_u32(const void* p) {
    uint32_t a;
    asm("{ .reg .u64 t; cvta.to.shared.u64 t, %1; cvt.u32.u64 %0, t; }"
        : "=r"(a) : "l"(p));
    return a;
}
__device__ __forceinline__ uint32_t mapa_rank(uint32_t laddr, int rank) {
    uint32_t r;
    asm("mapa.shared::cluster.u32 %0, %1, %2;" : "=r"(r) : "r"(laddr), "r"(rank));
    return r;
}
__device__ __forceinline__ void st_async_f32(uint32_t raddr, float v, uint32_t rmbar) {
    asm volatile(
        "st.async.weak.shared::cluster.mbarrier::complete_tx::bytes.b32 [%0], %1, [%2];"
        :: "r"(raddr), "r"(__float_as_uint(v)), "r"(rmbar) : "memory");
}
// fast sigmoid / tanh built on MUFU (EX2 + RCP); rel err ~1e-6 — safe vs 1e-3
__device__ __forceinline__ float fast_sigmoid(float x) {
    return __fdividef(1.f, 1.f + __expf(-x));
}
__device__ __forceinline__ float fast_tanh(float x) {
    return __fdividef(2.f, 1.f + __expf(-2.f * x)) - 1.f;
}
// packed f32x2 FMA (Blackwell FFMA2): d = a*b + d
__device__ __forceinline__ void fma2(unsigned long long& d,
                                     unsigned long long a, unsigned long long b) {
    asm("fma.rn.f32x2 %0, %1, %2, %0;" : "+l"(d) : "l"(a), "l"(b));
}
__device__ __forceinline__ unsigned long long pk2(float a, float b) {
    unsigned long long r;
    asm("mov.b64 %0, {%1, %2};" : "=l"(r) : "f"(a), "f"(b));
    return r;
}
__device__ __forceinline__ void unpk2(unsigned long long v, float& lo, float& hi) {
    asm("mov.b64 {%0, %1}, %2;" : "=f"(lo), "=f"(hi) : "l"(v));
}

// ---------------- 1. embedding gather ----------------------------------------
__global__ void embed_kernel(const int* __restrict__ x, const float* __restrict__ emb) {
    int m = blockIdx.x;
    int tok = x[m];
    float4 v = *(const float4*)(emb + (size_t)tok * 256 + threadIdx.x * 4);
    *(float4*)(g_cat + (size_t)m * 512 + threadIdx.x * 4) = v;
}

// ---------------- fused mix + weighted GEMM (TN, per batch, fp32) ------------
__global__ void __launch_bounds__(256) wgemm_kernel(
    const float* __restrict__ G, const float* __restrict__ Gp,
    const float* __restrict__ mw)
{
    int b = blockIdx.z;
    const float* A0 = G  + (size_t)b * 3 * 262144;
    const float* P0 = Gp + (size_t)b * 3 * 262144;
    const float* Bp = g_cat + (size_t)b * 262144;
    float* C        = g_cat + (size_t)b * 262144 + 256;
    float w0 = mw[0], w1 = mw[1], w2 = mw[2];
    float u0 = 1.f - w0, u1 = 1.f - w1, u2 = 1.f - w2;

    __shared__ __align__(16) float As[16][132];
    __shared__ __align__(16) float Bs[16][68];
    int tid = threadIdx.x;
    int m0b = blockIdx.x * 128, n0b = blockIdx.y * 64;
    int tm = tid >> 4, tn = tid & 15;
    int akk = tid >> 4, amc = (tid & 15) * 8;
    int bkk = tid >> 4, bnc = (tid & 15) * 4;

    float acc[8][4];
#pragma unroll
    for (int i = 0; i < 8; ++i)
#pragma unroll
        for (int j = 0; j < 4; ++j) acc[i][j] = 0.f;

    for (int k0 = 0; k0 < 512; k0 += 16) {
        size_t off = (size_t)(k0 + akk) * 512 + m0b + amc;
        float4 m0, m1;
        {
            float4 ga0 = *(const float4*)(A0 + off);
            float4 ga1 = *(const float4*)(A0 + off + 4);
            float4 pa0 = *(const float4*)(P0 + off);
            float4 pa1 = *(const float4*)(P0 + off + 4);
            float4 gb0 = *(const float4*)(A0 + 262144 + off);
            float4 gb1 = *(const float4*)(A0 + 262144 + off + 4);
            float4 pb0 = *(const float4*)(P0 + 262144 + off);
            float4 pb1 = *(const float4*)(P0 + 262144 + off + 4);
            float4 gc0 = *(const float4*)(A0 + 524288 + off);
            float4 gc1 = *(const float4*)(A0 + 524288 + off + 4);
            float4 pc0 = *(const float4*)(P0 + 524288 + off);
            float4 pc1 = *(const float4*)(P0 + 524288 + off + 4);
            m0.x = w0*ga0.x + u0*pa0.x + w1*gb0.x + u1*pb0.x + w2*gc0.x + u2*pc0.x;
            m0.y = w0*ga0.y + u0*pa0.y + w1*gb0.y + u1*pb0.y + w2*gc0.y + u2*pc0.y;
            m0.z = w0*ga0.z + u0*pa0.z + w1*gb0.z + u1*pb0.z + w2*gc0.z + u2*pc0.z;
            m0.w = w0*ga0.w + u0*pa0.w + w1*gb0.w + u1*pb0.w + w2*gc0.w + u2*pc0.w;
            m1.x = w0*ga1.x + u0*pa1.x + w1*gb1.x + u1*pb1.x + w2*gc1.x + u2*pc1.x;
            m1.y = w0*ga1.y + u0*pa1.y + w1*gb1.y + u1*pb1.y + w2*gc1.y + u2*pc1.y;
            m1.z = w0*ga1.z + u0*pa1.z + w1*gb1.z + u1*pb1.z + w2*gc1.z + u2*pc1.z;
            m1.w = w0*ga1.w + u0*pa1.w + w1*gb1.w + u1*pb1.w + w2*gc1.w + u2*pc1.w;
        }
        float4 bv = *(const float4*)(Bp + (size_t)(k0 + bkk) * 512 + n0b + bnc);
        __syncthreads();
        *(float4*)&As[akk][amc]     = m0;
        *(float4*)&As[akk][amc + 4] = m1;
        *(float4*)&Bs[bkk][bnc]     = bv;
        __syncthreads();
#pragma unroll
        for (int kk = 0; kk < 16; ++kk) {
            float a8[8], b4[4];
            *(float4*)&a8[0] = *(const float4*)&As[kk][tm * 8];
            *(float4*)&a8[4] = *(const float4*)&As[kk][tm * 8 + 4];
            *(float4*)&b4[0] = *(const float4*)&Bs[kk][tn * 4];
#pragma unroll
            for (int i = 0; i < 8; ++i)
#pragma unroll
                for (int j = 0; j < 4; ++j)
                    acc[i][j] = fmaf(a8[i], b4[j], acc[i][j]);
        }
    }
#pragma unroll
    for (int i = 0; i < 8; ++i) {
        size_t row = (size_t)(m0b + tm * 8 + i) * 512 + n0b + tn * 4;
        float4 v = {acc[i][0], acc[i][1], acc[i][2], acc[i][3]};
        *(float4*)(C + row) = v;
    }
}

// ---------------- double-buffered NT GEMM (128x64 tile, FFMA2 core) ----------
// MODE: 0 plain, 1 +bias, 2 tanh(+bias)
template<int MODE>
__global__ void __launch_bounds__(256) gemm_nt(
    const float* __restrict__ A, int lda,
    const float* __restrict__ B, int ldb,
    float* __restrict__ C, int ldc, int K,
    const float* __restrict__ bias)
{
    __shared__ __align__(16) float As[2][16][132];
    __shared__ __align__(16) float Bs[2][16][68];
    int tid = threadIdx.x;
    int m0b = blockIdx.x * 128, n0b = blockIdx.y * 64;
    int tm = tid >> 4, tn = tid & 15;
    int ar = tid >> 1, akc = (tid & 1) * 8;
    int bn = tid >> 2, bkc = (tid & 3) * 4;
    const float* Ap  = A + (size_t)(m0b + ar) * lda + akc;
    const float* Bpp = B + (size_t)(n0b + bn) * ldb + bkc;

    float4 a0 = *(const float4*)(Ap);
    float4 a1 = *(const float4*)(Ap + 4);
    float4 b0 = *(const float4*)(Bpp);

    auto stage = [&](int buf) {
        As[buf][akc+0][ar] = a0.x; As[buf][akc+1][ar] = a0.y;
        As[buf][akc+2][ar] = a0.z; As[buf][akc+3][ar] = a0.w;
        As[buf][akc+4][ar] = a1.x; As[buf][akc+5][ar] = a1.y;
        As[buf][akc+6][ar] = a1.z; As[buf][akc+7][ar] = a1.w;
        Bs[buf][bkc+0][bn] = b0.x; Bs[buf][bkc+1][bn] = b0.y;
        Bs[buf][bkc+2][bn] = b0.z; Bs[buf][bkc+3][bn] = b0.w;
    };
    stage(0);
    __syncthreads();

    unsigned long long acc2[8][2];
#pragma unroll
    for (int i = 0; i < 8; ++i) { acc2[i][0] = 0ull; acc2[i][1] = 0ull; }

    int nt = K >> 4;
    for (int t = 0; t < nt; ++t) {
        int cur = t & 1;
        if (t + 1 < nt) {
            const float* Ap2  = Ap  + (t + 1) * 16;
            const float* Bpp2 = Bpp + (t + 1) * 16;
            a0 = *(const float4*)(Ap2);
            a1 = *(const float4*)(Ap2 + 4);
            b0 = *(const float4*)(Bpp2);
        }
#pragma unroll
        for (int kk = 0; kk < 16; ++kk) {
            float a8[8], b4[4];
            *(float4*)&a8[0] = *(const float4*)&As[cur][kk][tm * 8];
            *(float4*)&a8[4] = *(const float4*)&As[cur][kk][tm * 8 + 4];
            *(float4*)&b4[0] = *(const float4*)&Bs[cur][kk][tn * 4];
            unsigned long long bb0 = pk2(b4[0], b4[1]);
            unsigned long long bb1 = pk2(b4[2], b4[3]);
#pragma unroll
            for (int i = 0; i < 8; ++i) {
                unsigned long long aa = pk2(a8[i], a8[i]);
                fma2(acc2[i][0], aa, bb0);
                fma2(acc2[i][1], aa, bb1);
            }
        }
        if (t + 1 < nt) {
            stage(cur ^ 1);
            __syncthreads();
        }
    }

    float bias4[4] = {0.f, 0.f, 0.f, 0.f};
    if (MODE >= 1) {
#pragma unroll
        for (int j = 0; j < 4; ++j) bias4[j] = bias[n0b + tn * 4 + j];
    }
#pragma unroll
    for (int i = 0; i < 8; ++i) {
        size_t row = (size_t)(m0b + tm * 8 + i) * ldc + n0b + tn * 4;
        float vv[4];
        unpk2(acc2[i][0], vv[0], vv[1]);
        unpk2(acc2[i][1], vv[2], vv[3]);
#pragma unroll
        for (int j = 0; j < 4; ++j) {
            float v = vv[j] + bias4[j];
            if (MODE == 2) v = tanhf(v);
            vv[j] = v;
        }
        float4 v4 = {vv[0], vv[1], vv[2], vv[3]};
        *(float4*)(C + row) = v4;
    }
}

// ---------------- fused GLU dual GEMM (FFMA2 core) ---------------------------
__global__ void __launch_bounds__(256) gemm_glu(
    const float* __restrict__ A, int lda,
    const float* __restrict__ B1, const float* __restrict__ B2, int ldb,
    float* __restrict__ C, int ldc, int K)
{
    __shared__ __align__(16) float As[2][16][132];
    __shared__ __align__(16) float Bs1[2][16][68];
    __shared__ __align__(16) float Bs2[2][16][68];
    int tid = threadIdx.x;
    int m0b = blockIdx.x * 128, n0b = blockIdx.y * 64;
    int tm = tid >> 4, tn = tid & 15;
    int ar = tid >> 1, akc = (tid & 1) * 8;
    int bn = tid >> 2, bkc = (tid & 3) * 4;
    const float* Ap  = A  + (size_t)(m0b + ar) * lda + akc;
    const float* Bp1 = B1 + (size_t)(n0b + bn) * ldb + bkc;
    const float* Bp2 = B2 + (size_t)(n0b + bn) * ldb + bkc;

    float4 a0 = *(const float4*)(Ap);
    float4 a1 = *(const float4*)(Ap + 4);
    float4 b0 = *(const float4*)(Bp1);
    float4 c0 = *(const float4*)(Bp2);

    auto stage = [&](int buf) {
        As[buf][akc+0][ar] = a0.x; As[buf][akc+1][ar] = a0.y;
        As[buf][akc+2][ar] = a0.z; As[buf][akc+3][ar] = a0.w;
        As[buf][akc+4][ar] = a1.x; As[buf][akc+5][ar] = a1.y;
        As[buf][akc+6][ar] = a1.z; As[buf][akc+7][ar] = a1.w;
        Bs1[buf][bkc+0][bn] = b0.x; Bs1[buf][bkc+1][bn] = b0.y;
        Bs1[buf][bkc+2][bn] = b0.z; Bs1[buf][bkc+3][bn] = b0.w;
        Bs2[buf][bkc+0][bn] = c0.x; Bs2[buf][bkc+1][bn] = c0.y;
        Bs2[buf][bkc+2][bn] = c0.z; Bs2[buf][bkc+3][bn] = c0.w;
    };
    stage(0);
    __syncthreads();

    unsigned long long acc1[8][2], acc2[8][2];
#pragma unroll
    for (int i = 0; i < 8; ++i) {
        acc1[i][0] = 0ull; acc1[i][1] = 0ull;
        acc2[i][0] = 0ull; acc2[i][1] = 0ull;
    }

    int nt = K >> 4;
    for (int t = 0; t < nt; ++t) {
        int cur = t & 1;
        if (t + 1 < nt) {
            a0 = *(const float4*)(Ap  + (t + 1) * 16);
            a1 = *(const float4*)(Ap  + (t + 1) * 16 + 4);
            b0 = *(const float4*)(Bp1 + (t + 1) * 16);
            c0 = *(const float4*)(Bp2 + (t + 1) * 16);
        }
#pragma unroll
        for (int kk = 0; kk < 16; ++kk) {
            float a8[8], b4[4], c4[4];
            *(float4*)&a8[0] = *(const float4*)&As[cur][kk][tm * 8];
            *(float4*)&a8[4] = *(const float4*)&As[cur][kk][tm * 8 + 4];
            *(float4*)&b4[0] = *(const float4*)&Bs1[cur][kk][tn * 4];
            *(float4*)&c4[0] = *(const float4*)&Bs2[cur][kk][tn * 4];
            unsigned long long bb0 = pk2(b4[0], b4[1]);
            unsigned long long bb1 = pk2(b4[2], b4[3]);
            unsigned long long cc0 = pk2(c4[0], c4[1]);
            unsigned long long cc1 = pk2(c4[2], c4[3]);
#pragma unroll
            for (int i = 0; i < 8; ++i) {
                unsigned long long aa = pk2(a8[i], a8[i]);
                fma2(acc1[i][0], aa, bb0);
                fma2(acc1[i][1], aa, bb1);
                fma2(acc2[i][0], aa, cc0);
                fma2(acc2[i][1], aa, cc1);
            }
        }
        if (t + 1 < nt) {
            stage(cur ^ 1);
            __syncthreads();
        }
    }
#pragma unroll
    for (int i = 0; i < 8; ++i) {
        size_t row = (size_t)(m0b + tm * 8 + i) * ldc + n0b + tn * 4;
        float p0, p1, p2, p3, q0, q1, q2, q3;
        unpk2(acc1[i][0], p0, p1);
        unpk2(acc1[i][1], p2, p3);
        unpk2(acc2[i][0], q0, q1);
        unpk2(acc2[i][1], q2, q3);
        float4 v;
        v.x = p0 * fast_sigmoid(q0);
        v.y = p1 * fast_sigmoid(q1);
        v.z = p2 * fast_sigmoid(q2);
        v.w = p3 * fast_sigmoid(q3);
        *(float4*)(C + row) = v;
    }
}

// ---------------- GRU scan: butterfly + distributed bcast (R15 exact) --------
__global__ void __launch_bounds__(256, 1) __cluster_dims__(8, 1, 1)
scan_kernel(const float* __restrict__ xg, const float* __restrict__ Whh,
            const float* __restrict__ bhh, const float* __restrict__ h0)
{
    __shared__ __align__(16) float h[2][256];
    __shared__ __align__(8) unsigned long long mbar[2];
    int tid  = threadIdx.x;
    int rank = blockIdx.x & 7;
    int b    = blockIdx.x >> 3;
    int pair = tid >> 3;
    int sub  = tid & 7;
    int j    = rank * 32 + pair;

    float4 w[3][8];
#pragma unroll
    for (int g = 0; g < 3; ++g) {
        const float* row = Whh + (size_t)(g * 256 + j) * 256;
#pragma unroll
        for (int i = 0; i < 8; ++i)
            w[g][i] = *(const float4*)(row + i * 32 + sub * 4);
    }
    float b_r = bhh[j], b_z = bhh[256 + j], b_n = bhh[512 + j];

    uint32_t barloc[2] = { smem_u32(&mbar[0]), smem_u32(&mbar[1]) };
    if (tid == 0) {
        asm volatile("mbarrier.init.shared.b64 [%0], 1;" :: "r"(barloc[0]) : "memory");
        asm volatile("mbarrier.init.shared.b64 [%0], 1;" :: "r"(barloc[1]) : "memory");
    }
    h[0][tid] = h0[b * 256 + tid];
    uint32_t hbase[2] = { smem_u32(&h[0][0]), smem_u32(&h[1][0]) };

    uint32_t raddr0 = mapa_rank(hbase[0] + (uint32_t)j * 4u, sub);
    uint32_t raddr1 = mapa_rank(hbase[1] + (uint32_t)j * 4u, sub);
    uint32_t rmbar0 = mapa_rank(barloc[0], sub);
    uint32_t rmbar1 = mapa_rank(barloc[1], sub);
    __syncthreads();
    asm volatile("barrier.cluster.arrive.aligned;" ::: "memory");
    asm volatile("barrier.cluster.wait.aligned;"  ::: "memory");

    const float* xrow0 = xg + (size_t)(b * 512) * 768;
    float xr = xrow0[j], xz = xrow0[256 + j], xn = xrow0[512 + j];

    for (int t = 0; t < 512; ++t) {
        int p = t & 1;
        if (tid == 0) {
            asm volatile("mbarrier.arrive.expect_tx.shared.b64 _, [%0], 1024;"
                         :: "r"(barloc[p]) : "memory");
        }
        float hold = h[p][j];
        float ar = 0.f, az = 0.f, an = 0.f;
#pragma unroll
        for (int i = 0; i < 8; ++i) {
            float4 hv = *(const float4*)&h[p][i * 32 + sub * 4];
            ar = fmaf(w[0][i].x, hv.x, ar); ar = fmaf(w[0][i].y, hv.y, ar);
            ar = fmaf(w[0][i].z, hv.z, ar); ar = fmaf(w[0][i].w, hv.w, ar);
            az = fmaf(w[1][i].x, hv.x, az); az = fmaf(w[1][i].y, hv.y, az);
            az = fmaf(w[1][i].z, hv.z, az); az = fmaf(w[1][i].w, hv.w, az);
            an = fmaf(w[2][i].x, hv.x, an); an = fmaf(w[2][i].y, hv.y, an);
            an = fmaf(w[2][i].z, hv.z, an); an = fmaf(w[2][i].w, hv.w, an);
        }
#pragma unroll
        for (int off = 4; off; off >>= 1) {
            ar += __shfl_xor_sync(0xffffffffu, ar, off, 8);
            az += __shfl_xor_sync(0xffffffffu, az, off, 8);
            an += __shfl_xor_sync(0xffffffffu, an, off, 8);
        }
        float r_ = fast_sigmoid(xr + ar + b_r);
        float z_ = fast_sigmoid(xz + az + b_z);
        float n_ = fast_tanh(xn + r_ * (an + b_n));
        float hv = (1.f - z_) * n_ + z_ * hold;
        st_async_f32((p == 0) ? raddr1 : raddr0, hv, (p == 0) ? rmbar0 : rmbar1);
        if (sub == 0)
            g_out[(size_t)(b * 512 + t) * 256 + j] = hv;
        if (t < 511) {
            const float* xrow = xg + (size_t)(b * 512 + t + 1) * 768;
            xr = xrow[j]; xz = xrow[256 + j]; xn = xrow[512 + j];
        }
        {
            uint32_t parity = (uint32_t)((t >> 1) & 1);
            asm volatile(
                "{\n\t"
                ".reg .pred P1;\n\t"
                "WL_%=:\n\t"
                "mbarrier.try_wait.parity.acquire.cta.shared::cta.b64 P1, [%0], %1, 0x989680;\n\t"
                "@P1 bra.uni WD_%=;\n\t"
                "bra.uni WL_%=;\n\t"
                "WD_%=:\n\t"
                "}"
                :: "r"(barloc[p]), "r"(parity) : "memory");
        }
    }
}

// ---------------- attention logits: a = u @ W2^T + b2 ------------------------
__global__ void __launch_bounds__(256) logits_kernel(const float* __restrict__ W2,
                                                     const float* __restrict__ b2) {
    __shared__ float sW[8 * 256];
    for (int i = threadIdx.x; i < 2048; i += 256) sW[i] = W2[i];
    __syncthreads();
    int warp = threadIdx.x >> 5, lane = threadIdx.x & 31;
    int m = blockIdx.x * 8 + warp;
    const float* ur = g_u + (size_t)m * 256;
    float uv[8];
#pragma unroll
    for (int i = 0; i < 8; ++i) uv[i] = ur[i * 32 + lane];
#pragma unroll
    for (int hh = 0; hh < 8; ++hh) {
        float acc = 0.f;
#pragma unroll
        for (int i = 0; i < 8; ++i) acc = fmaf(uv[i], sW[hh * 256 + i * 32 + lane], acc);
#pragma unroll
        for (int off = 16; off; off >>= 1) acc += __shfl_down_sync(0xffffffffu, acc, off);
        if (lane == 0) g_a[(size_t)m * 8 + hh] = acc + b2[hh];
    }
}

// ---------------- masked softmax over T --------------------------------------
__global__ void softmax_kernel(const int* __restrict__ lengths, float* __restrict__ att) {
    int bh = blockIdx.x, b = bh >> 3, hh = bh & 7;
    int t = threadIdx.x;
    int len = lengths[b];
    float v = (t < len) ? g_a[(size_t)(b * 512 + t) * 8 + hh] : -1e30f;
    __shared__ float red[16];
    __shared__ float bc[2];
    float m = v;
#pragma unroll
    for (int o = 16; o; o >>= 1) m = fmaxf(m, __shfl_xor_sync(0xffffffffu, m, o));
    if ((t & 31) == 0) red[t >> 5] = m;
    __syncthreads();
    if (t == 0) {
        float mm = red[0];
        for (int i = 1; i < 16; ++i) mm = fmaxf(mm, red[i]);
        bc[0] = mm;
    }
    __syncthreads();
    float e = __expf(v - bc[0]);
    float s = e;
#pragma unroll
    for (int o = 16; o; o >>= 1) s += __shfl_xor_sync(0xffffffffu, s, o);
    __syncthreads();
    if ((t & 31) == 0) red[t >> 5] = s;
    __syncthreads();
    if (t == 0) {
        float ss = 0.f;
        for (int i = 0; i < 16; ++i) ss += red[i];
        bc[1] = ss;
    }
    __syncthreads();
    att[(size_t)bh * 512 + t] = e / bc[1];
}

// ---------------- sent + avg (+hn copy) --------------------------------------
__global__ void __launch_bounds__(256) sent_kernel(const float* __restrict__ att,
                                                   float* __restrict__ out_hn) {
    int b = blockIdx.x, q = blockIdx.y;
    __shared__ float sat[8][512];
    __shared__ float sred[4][8][64];
    int tid = threadIdx.x;
    for (int i = tid; i < 4096; i += 256) sat[i >> 9][i & 511] = att[(size_t)b * 4096 + i];
    __syncthreads();
    int dl = tid & 63, tc = tid >> 6;
    int d = q * 64 + dl;
    const float* orow = g_out + (size_t)b * 512 * 256;
    float acc[8] = {0.f,0.f,0.f,0.f,0.f,0.f,0.f,0.f};
    for (int t = tc * 128; t < tc * 128 + 128; ++t) {
        float ov = orow[(size_t)t * 256 + d];
#pragma unroll
        for (int hh = 0; hh < 8; ++hh) acc[hh] = fmaf(sat[hh][t], ov, acc[hh]);
    }
#pragma unroll
    for (int hh = 0; hh < 8; ++hh) sred[tc][hh][dl] = acc[hh];
    __syncthreads();
    if (tc == 0) {
        float s = 0.f;
#pragma unroll
        for (int hh = 0; hh < 8; ++hh)
            s += sred[0][hh][dl] + sred[1][hh][dl] + sred[2][hh][dl] + sred[3][hh][dl];
        g_sent[b * 256 + d] = s * 0.125f;
        out_hn[b * 256 + d] = orow[(size_t)511 * 256 + d];
    }
}

// ---------------- final FC ---------------------------------------------------
__global__ void fc_kernel(const float* __restrict__ Wf, const float* __restrict__ bf,
                          float* __restrict__ out_main) {
    int b = blockIdx.x;
    __shared__ float sv[256];
    sv[threadIdx.x] = g_sent[b * 256 + threadIdx.x];
    __syncthreads();
    if (threadIdx.x < 10) {
        float s = bf[threadIdx.x];
        for (int k = 0; k < 256; ++k) s = fmaf(Wf[threadIdx.x * 256 + k], sv[k], s);
        out_main[b * 10 + threadIdx.x] = s;
    }
}

// ============================================================================
extern "C" void kernel_launch(void* const* d_in, const int* in_sizes, int n_in,
                              void* d_out, int out_size) {
    const int*   x    = (const int*)  d_in[0];
    const int*   len  = (const int*)  d_in[1];
    const float* h0   = (const float*)d_in[2];
    const float* emb  = (const float*)d_in[3];
    const float* G    = (const float*)d_in[4];
    const float* Gp   = (const float*)d_in[5];
    const float* mw   = (const float*)d_in[6];
    const float* Wc1  = (const float*)d_in[7];
    const float* Wc2  = (const float*)d_in[8];
    const float* W_ih = (const float*)d_in[9];
    const float* W_hh = (const float*)d_in[10];
    const float* b_ih = (const float*)d_in[11];
    const float* b_hh = (const float*)d_in[12];
    const float* W1   = (const float*)d_in[13];
    const float* b1   = (const float*)d_in[14];
    const float* W2   = (const float*)d_in[15];
    const float* b2   = (const float*)d_in[16];
    const float* Wf   = (const float*)d_in[17];
    const float* bf   = (const float*)d_in[18];

    float* out      = (float*)d_out;
    float* out_main = out;
    float* out_hn   = out + 160;
    float* out_att  = out + 160 + 4096;

    void* p;
    cudaGetSymbolAddress(&p, g_cat);  float* pcat  = (float*)p;
    cudaGetSymbolAddress(&p, g_next); float* pnext = (float*)p;
    cudaGetSymbolAddress(&p, g_xg);   float* pxg   = (float*)p;
    cudaGetSymbolAddress(&p, g_out);  float* pout  = (float*)p;
    cudaGetSymbolAddress(&p, g_u);    float* pu    = (float*)p;

    // 1. embedding gather
    embed_kernel<<<8192, 64>>>(x, emb);
    // 2+3. fused mix + weighted GEMM
    wgemm_kernel<<<dim3(4, 4, 16), 256>>>(G, Gp, mw);
    // 4+5. fused GLU: next = (cat@Wc1^T) * sigmoid(cat@Wc2^T)
    gemm_glu<<<dim3(64, 4), 256>>>(pcat, 512, Wc1, Wc2, 512, pnext, 256, 512);
    // 6. xg = next @ W_ih^T + b_ih
    gemm_nt<1><<<dim3(64, 12), 256>>>(pnext, 256, W_ih, 256, pxg, 768, 256, b_ih);
    // 7. GRU scan (R15 exact)
    scan_kernel<<<128, 256>>>(pxg, W_hh, b_hh, h0);
    // 8. u = tanh(out @ W1^T + b1)
    gemm_nt<2><<<dim3(64, 4), 256>>>(pout, 256, W1, 256, pu, 256, 256, b1);
    // 9. logits
    logits_kernel<<<1024, 256>>>(W2, b2);
    // 10. masked softmax
    softmax_kernel<<<128, 512>>>(len, out_att);
    // 11. sent + avg + hn
    sent_kernel<<<dim3(16, 4), 256>>>(out_att, out_hn);
    // 12. final FC
    fc_kernel<<<16, 256>>>(Wf, bf, out_main);
}